// round 12
// baseline (speedup 1.0000x reference)
#include <cuda_runtime.h>
#include <cuda_fp16.h>
#include <cstdint>

#define SP 7
#define MM 8
#define DD 1008
#define KQ 1024          // DD padded for int8 k32 chunks
#define H0 256
#define H1 192
#define H2 160
#define NMAX 50400
#define GMAX (NMAX / SP)
#define BATCH (SP * MM)
#define HB 112
#define EB 1024

// ---------------- scratch (device globals; no allocation allowed) ------------
__device__ int d_idx[NMAX];
__device__ int d_hist[HB * SP];
__device__ int d_off[HB * SP];

// L0: int8 two-limb (15-bit) rows [Ah 1024 | Al 1024], per-row scales
__device__ __align__(16) int8_t d_a0q[(size_t)NMAX * 2 * KQ];
__device__ __align__(16) int8_t d_w0q[(size_t)BATCH * H0 * 2 * KQ];
__device__ float d_sa0[NMAX];
__device__ float d_sb0[BATCH * H0];
// L1/L2: fp16 [hi | lo] split activations, single-fp16 weights
__device__ __align__(16) __half d_w1[(size_t)BATCH * H1 * H0];
__device__ __align__(16) __half d_w2[(size_t)BATCH * H2 * H1];
__device__ __align__(16) __half d_a1[(size_t)BATCH * GMAX * 2 * H0];
__device__ __align__(16) __half d_a2[(size_t)BATCH * GMAX * 2 * H1];
__device__ float d_ps[(size_t)BATCH * GMAX * 6];
__device__ float d_part[EB];

__device__ __forceinline__ float celu_f(float x) {
    return x > 0.f ? x : 0.1f * expm1f(x * 10.0f);
}

// ---------------- PTX helpers (all baseline sm_80+ features) ------------------
__device__ __forceinline__ uint32_t smem_u32(const void* p) {
    uint32_t a;
    asm("{ .reg .u64 t; cvta.to.shared.u64 t, %1; cvt.u32.u64 %0, t; }"
        : "=r"(a) : "l"(p));
    return a;
}
__device__ __forceinline__ void cp16(uint32_t s, const void* g) {
    asm volatile("cp.async.cg.shared.global [%0], [%1], 16;" :: "r"(s), "l"(g));
}
__device__ __forceinline__ void cp_commit() {
    asm volatile("cp.async.commit_group;" ::: "memory");
}
template <int N>
__device__ __forceinline__ void cp_wait() {
    asm volatile("cp.async.wait_group %0;" :: "n"(N) : "memory");
}
__device__ __forceinline__ void ldsm_x4(uint32_t& r0, uint32_t& r1,
                                        uint32_t& r2, uint32_t& r3, uint32_t a) {
    asm volatile("ldmatrix.sync.aligned.m8n8.x4.shared.b16 {%0,%1,%2,%3}, [%4];"
                 : "=r"(r0), "=r"(r1), "=r"(r2), "=r"(r3) : "r"(a));
}
__device__ __forceinline__ void mma16816(float* c, const uint32_t* a, const uint32_t* b) {
    asm volatile(
        "mma.sync.aligned.m16n8k16.row.col.f32.f16.f16.f32 "
        "{%0,%1,%2,%3}, {%4,%5,%6,%7}, {%8,%9}, {%0,%1,%2,%3};"
        : "+f"(c[0]), "+f"(c[1]), "+f"(c[2]), "+f"(c[3])
        : "r"(a[0]), "r"(a[1]), "r"(a[2]), "r"(a[3]), "r"(b[0]), "r"(b[1]));
}
__device__ __forceinline__ void imma16832(int* c, const uint32_t* a, const uint32_t* b) {
    asm volatile(
        "mma.sync.aligned.m16n8k32.row.col.s32.s8.s8.s32 "
        "{%0,%1,%2,%3}, {%4,%5,%6,%7}, {%8,%9}, {%0,%1,%2,%3};"
        : "+r"(c[0]), "+r"(c[1]), "+r"(c[2]), "+r"(c[3])
        : "r"(a[0]), "r"(a[1]), "r"(a[2]), "r"(a[3]), "r"(b[0]), "r"(b[1]));
}

// ---------------- stable species bucketing (deterministic) -------------------
__global__ void k_hist(const int* __restrict__ sp, int n, int chunk) {
    __shared__ int h[SP];
    if (threadIdx.x < SP) h[threadIdx.x] = 0;
    __syncthreads();
    int b = blockIdx.x;
    int beg = b * chunk, end = min(n, beg + chunk);
    for (int i = beg + threadIdx.x; i < end; i += blockDim.x)
        atomicAdd(&h[sp[i]], 1);
    __syncthreads();
    if (threadIdx.x < SP) d_hist[b * SP + threadIdx.x] = h[threadIdx.x];
}
__global__ void k_scan(int G) {
    int s = threadIdx.x;
    if (s >= SP) return;
    int acc = s * G;
    for (int b = 0; b < HB; b++) { d_off[b * SP + s] = acc; acc += d_hist[b * SP + s]; }
}
__global__ void k_place(const int* __restrict__ sp, int n, int chunk) {
    if (threadIdx.x != 0) return;
    int b = blockIdx.x;
    int beg = b * chunk, end = min(n, beg + chunk);
    int loc[SP];
#pragma unroll
    for (int s = 0; s < SP; s++) loc[s] = d_off[b * SP + s];
    for (int i = beg; i < end; i++) d_idx[loc[sp[i]]++] = i;
}

// ---------------- prep: gather + int8 quantize AEV ---------------------------
__global__ void k_prep_aev_q(const float* __restrict__ aev) {
    __shared__ float buf[KQ];
    __shared__ float red[256];
    int r = blockIdx.x;
    const float* src = aev + (size_t)d_idx[r] * DD;
    int t = threadIdx.x;
    float m = 0.f;
    for (int k = t; k < KQ; k += 256) {
        float v = (k < DD) ? src[k] : 0.f;
        buf[k] = v;
        m = fmaxf(m, fabsf(v));
    }
    red[t] = m;
    __syncthreads();
    for (int s = 128; s > 0; s >>= 1) {
        if (t < s) red[t] = fmaxf(red[t], red[t + s]);
        __syncthreads();
    }
    float mx = red[0];
    float inv = mx > 0.f ? 16256.f / mx : 0.f;
    if (t == 0) d_sa0[r] = mx * (1.f / 16256.f);
    int8_t* dst = d_a0q + (size_t)r * (2 * KQ);
    for (int k = t; k < KQ; k += 256) {
        float q = rintf(buf[k] * inv);
        int ia = (int)rintf(q * (1.f / 128.f));
        int il = (int)q - (ia << 7);
        dst[k] = (int8_t)ia;
        dst[KQ + k] = (int8_t)il;
    }
}

// ---------------- W0 prep: per-row max, then transpose+quantize --------------
__global__ void k_wmax0(const float* __restrict__ W) {
    __shared__ float part[4][H0];
    int bm = blockIdx.x;
    int n = threadIdx.x, yq = threadIdx.y;
    const float* Wp = W + (size_t)bm * DD * H0 + n;
    int k0 = yq * 252, k1 = k0 + 252;
    float m = 0.f;
    for (int k = k0; k < k1; k++)
        m = fmaxf(m, fabsf(Wp[(size_t)k * H0]));
    part[yq][n] = m;
    __syncthreads();
    if (yq == 0) {
        m = fmaxf(fmaxf(part[0][n], part[1][n]), fmaxf(part[2][n], part[3][n]));
        d_sb0[bm * H0 + n] = m * (1.f / 16256.f);
    }
}

__global__ void k_wquant0(const float* __restrict__ W) {
    __shared__ float tile[32][33];
    int bm = blockIdx.z;
    int n0 = blockIdx.x * 32, k0 = blockIdx.y * 32;
    const float* Wp = W + (size_t)bm * DD * H0;
    for (int r = threadIdx.y; r < 32; r += 8) {
        int k = k0 + r;
        tile[r][threadIdx.x] = (k < DD) ? Wp[(size_t)k * H0 + n0 + threadIdx.x] : 0.f;
    }
    __syncthreads();
    for (int r = threadIdx.y; r < 32; r += 8) {
        int n = n0 + r;
        float sb = d_sb0[bm * H0 + n];
        float inv = sb > 0.f ? 1.f / sb : 0.f;
        float q = rintf(tile[threadIdx.x][r] * inv);
        int ia = (int)rintf(q * (1.f / 128.f));
        int il = (int)q - (ia << 7);
        size_t o = ((size_t)(bm * H0 + n)) * (2 * KQ) + k0 + threadIdx.x;
        d_w0q[o] = (int8_t)ia;
        d_w0q[o + KQ] = (int8_t)il;
    }
}

// ---------------- W1/W2 prep: transpose to [n][k], fp16 ----------------------
__global__ void k_wsplit(const float* __restrict__ W, int K, int N, int layer) {
    __shared__ float tile[32][33];
    int bm = blockIdx.z;
    int n0 = blockIdx.x * 32, k0 = blockIdx.y * 32;
    const float* Wp = W + (size_t)bm * K * N;
    for (int r = threadIdx.y; r < 32; r += 8) {
        int k = k0 + r, n = n0 + threadIdx.x;
        tile[r][threadIdx.x] = (k < K && n < N) ? Wp[(size_t)k * N + n] : 0.f;
    }
    __syncthreads();
    __half* O = (layer == 1) ? d_w1 : d_w2;
    for (int r = threadIdx.y; r < 32; r += 8) {
        int n = n0 + r, k = k0 + threadIdx.x;
        if (n < N && k < K)
            O[((size_t)bm * N + n) * (size_t)K + k] = __float2half(tile[threadIdx.x][r]);
    }
}

// ---------------- L0: int8 IMMA GEMM (3 products per k32 chunk) --------------
// D = sa*sb*(16384*Sum(Ah*Bh) + 128*Sum(Ah*Bl + Al*Bh))   [drop Al*Bl ~ 6e-5]
// Epilogue: +bias, CELU, fp16 hi/lo split store to d_a1.
__global__ void __launch_bounds__(256, 2)
k_mma0(const float* __restrict__ bias, int G) {
    constexpr int BM = 128, BN = 64;
    constexpr int TOTAL = KQ / 32;   // 32
    constexpr int NS = 3;

    // rows: [Ah 32B | Al 32B | 16B pad] = 80B pitch (odd*16B)
    __shared__ __align__(16) int8_t As[NS][BM][80];
    __shared__ __align__(16) int8_t Bs[NS][BN][80];

    const int t = threadIdx.x;
    const int lane = t & 31;
    const int wid = t >> 5;
    const int wr = wid >> 1;
    const int wn = wid & 1;
    const int bm = blockIdx.x;          // fastest: 8 models share A in L2
    const int gt = blockIdx.y * BM;
    const int ntb = blockIdx.z * BN;

    const size_t aBase = (size_t)(bm / MM) * G;

    const int arow = t >> 1, aseg = t & 1;
    const int growc = min(gt + arow, G - 1);
    const int8_t* aRow = d_a0q + (aBase + growc) * (size_t)(2 * KQ);
    const int brow = t >> 2, bpart = (t >> 1) & 1, bseg = t & 1;
    const int8_t* bRow = d_w0q + ((size_t)bm * H0 + ntb + brow) * (size_t)(2 * KQ);

    auto load_stage = [&](int st, int it) {
        const int k0 = it * 32;
        cp16(smem_u32(&As[st][arow][aseg * 16]), aRow + k0 + aseg * 16);
        cp16(smem_u32(&As[st][arow][32 + aseg * 16]), aRow + KQ + k0 + aseg * 16);
        cp16(smem_u32(&Bs[st][brow][bpart * 32 + bseg * 16]),
             bRow + bpart * KQ + k0 + bseg * 16);
        cp_commit();
    };

    int acc1[2][4][4], acc2[2][4][4];
#pragma unroll
    for (int i = 0; i < 2; i++)
#pragma unroll
        for (int j = 0; j < 4; j++)
#pragma unroll
            for (int k = 0; k < 4; k++) { acc1[i][j][k] = 0; acc2[i][j][k] = 0; }

    // ldmatrix offsets, 80B pitch
    const uint32_t aoff = (uint32_t)((wr * 32 + (lane & 15)) * 80 + (lane >> 4) * 16);
    const uint32_t boff4 = (uint32_t)(
        (wn * 32 + (lane & 7) + ((lane >> 4) << 3)) * 80 + (((lane >> 3) & 1) * 16));

#pragma unroll 1
    for (int s = 0; s < NS - 1; s++) load_stage(s, s);

#pragma unroll 1
    for (int i = 0; i < TOTAL; i++) {
        cp_wait<NS - 2>();
        __syncthreads();
        if (i + NS - 1 < TOTAL) load_stage((i + NS - 1) % NS, i + NS - 1);
        else cp_commit();

        const int st = i % NS;
        const uint32_t ab = smem_u32(&As[st][0][0]);
        const uint32_t bb = smem_u32(&Bs[st][0][0]);
        uint32_t ah[2][4], al[2][4], bf[4][2];
#pragma unroll
        for (int mt = 0; mt < 2; mt++) {
            ldsm_x4(ah[mt][0], ah[mt][1], ah[mt][2], ah[mt][3],
                    ab + aoff + mt * 16 * 80);
            ldsm_x4(al[mt][0], al[mt][1], al[mt][2], al[mt][3],
                    ab + aoff + mt * 16 * 80 + 32);
        }
        // Bh products
        ldsm_x4(bf[0][0], bf[0][1], bf[1][0], bf[1][1], bb + boff4);
        ldsm_x4(bf[2][0], bf[2][1], bf[3][0], bf[3][1], bb + boff4 + 16 * 80);
#pragma unroll
        for (int mt = 0; mt < 2; mt++)
#pragma unroll
            for (int nt = 0; nt < 4; nt++) {
                imma16832(acc1[mt][nt], ah[mt], bf[nt]);
                imma16832(acc2[mt][nt], al[mt], bf[nt]);
            }
        // Bl product (reuse bf regs)
        ldsm_x4(bf[0][0], bf[0][1], bf[1][0], bf[1][1], bb + boff4 + 32);
        ldsm_x4(bf[2][0], bf[2][1], bf[3][0], bf[3][1], bb + boff4 + 16 * 80 + 32);
#pragma unroll
        for (int mt = 0; mt < 2; mt++)
#pragma unroll
            for (int nt = 0; nt < 4; nt++)
                imma16832(acc2[mt][nt], ah[mt], bf[nt]);
    }

    // -------- epilogue: dequant + bias + CELU + fp16 hi/lo store -------------
    const float* bp = bias + (size_t)bm * H0;
#pragma unroll
    for (int mt = 0; mt < 2; mt++) {
#pragma unroll
        for (int half = 0; half < 2; half++) {
            const int grow = gt + wr * 32 + mt * 16 + (lane >> 2) + half * 8;
            if (grow >= G) continue;
            const float sa = __ldg(&d_sa0[aBase + grow]);
            size_t rb = ((size_t)bm * G + grow) * (size_t)(2 * H0);
#pragma unroll
            for (int nt = 0; nt < 4; nt++) {
                const int col = ntb + wn * 32 + nt * 8 + (lane & 3) * 2;
                const float sb0 = __ldg(&d_sb0[bm * H0 + col]);
                const float sb1 = __ldg(&d_sb0[bm * H0 + col + 1]);
                float r0 = (float)acc1[mt][nt][half * 2 + 0] * 16384.f
                         + (float)acc2[mt][nt][half * 2 + 0] * 128.f;
                float r1 = (float)acc1[mt][nt][half * 2 + 1] * 16384.f
                         + (float)acc2[mt][nt][half * 2 + 1] * 128.f;
                float v0 = r0 * (sa * sb0) + __ldg(bp + col);
                float v1 = r1 * (sa * sb1) + __ldg(bp + col + 1);
                v0 = celu_f(v0);
                v1 = celu_f(v1);
                __half h0 = __float2half(v0);
                __half h1 = __float2half(v1);
                __half2 hh, ll;
                hh.x = h0; hh.y = h1;
                ll.x = __float2half(v0 - __half2float(h0));
                ll.y = __float2half(v1 - __half2float(h1));
                *(__half2*)(d_a1 + rb + col) = hh;
                *(__half2*)(d_a1 + rb + H0 + col) = ll;
            }
        }
    }
}

// ---------------- L1/L2: fp16 HMMA GEMM (2 products per chunk) ---------------
template <int K, int NOUT, int LAYER>
__global__ void __launch_bounds__(256, 2)
k_mma(const float* __restrict__ bias, const float* __restrict__ w3g, int G) {
    constexpr int BM = 128, BN = 64;
    constexpr int TOTAL = K / 16;
    constexpr int NS = 3;

    __shared__ __align__(16) __half As[NS][BM][40];
    __shared__ __align__(16) __half Bs[NS][BN][24];

    const int t = threadIdx.x;
    const int lane = t & 31;
    const int wid = t >> 5;
    const int wr = wid >> 1;
    const int wn = wid & 1;
    const int bm = blockIdx.x;
    const int gt = blockIdx.y * BM;
    const int ytile = blockIdx.z;
    const int ntb = ytile * BN;

    const __half* Ag = (LAYER == 1) ? d_a1 : d_a2;
    const __half* Wg = (LAYER == 1) ? d_w1 : d_w2;
    const size_t aBase = (size_t)bm * G;

    const int arow = t >> 1, aseg = t & 1;
    const int growc = min(gt + arow, G - 1);
    const __half* aSrc = Ag + (aBase + growc) * (size_t)(2 * K) + aseg * 8;
    const int brow = t >> 1, bseg = t & 1;
    const int bn = min(ntb + brow, NOUT - 1);
    const __half* bSrc = Wg + ((size_t)bm * NOUT + bn) * (size_t)K + bseg * 8;

    auto load_stage = [&](int st, int it) {
        const int k0 = it * 16;
        cp16(smem_u32(&As[st][arow][aseg * 8]), aSrc + k0);
        cp16(smem_u32(&As[st][arow][16 + aseg * 8]), aSrc + K + k0);
        if (t < 128) cp16(smem_u32(&Bs[st][brow][bseg * 8]), bSrc + k0);
        cp_commit();
    };

    float acc[2][4][4];
#pragma unroll
    for (int i = 0; i < 2; i++)
#pragma unroll
        for (int j = 0; j < 4; j++)
#pragma unroll
            for (int k = 0; k < 4; k++) acc[i][j][k] = 0.f;

    const uint32_t aoff = (uint32_t)((wr * 32 + (lane & 15)) * 80 + (lane >> 4) * 16);
    const uint32_t boff4 = (uint32_t)(
        (wn * 32 + (lane & 7) + ((lane >> 4) << 3)) * 48 + (((lane >> 3) & 1) * 16));

#pragma unroll 1
    for (int s = 0; s < NS - 1; s++) load_stage(s, s);

#pragma unroll 1
    for (int i = 0; i < TOTAL; i++) {
        cp_wait<NS - 2>();
        __syncthreads();
        if (i + NS - 1 < TOTAL) load_stage((i + NS - 1) % NS, i + NS - 1);
        else cp_commit();

        const int st = i % NS;
        const uint32_t ab = smem_u32(&As[st][0][0]);
        const uint32_t bb = smem_u32(&Bs[st][0][0]);
        uint32_t ah[2][4], al[2][4], bf[4][2];
#pragma unroll
        for (int mt = 0; mt < 2; mt++) {
            ldsm_x4(ah[mt][0], ah[mt][1], ah[mt][2], ah[mt][3],
                    ab + aoff + mt * 16 * 80);
            ldsm_x4(al[mt][0], al[mt][1], al[mt][2], al[mt][3],
                    ab + aoff + mt * 16 * 80 + 32);
        }
        ldsm_x4(bf[0][0], bf[0][1], bf[1][0], bf[1][1], bb + boff4);
        ldsm_x4(bf[2][0], bf[2][1], bf[3][0], bf[3][1], bb + boff4 + 16 * 48);
#pragma unroll
        for (int mt = 0; mt < 2; mt++)
#pragma unroll
            for (int nt = 0; nt < 4; nt++) {
                mma16816(acc[mt][nt], ah[mt], bf[nt]);
                mma16816(acc[mt][nt], al[mt], bf[nt]);
            }
    }

    const float* bp = bias + (size_t)bm * NOUT;
    if (LAYER == 1) {
#pragma unroll
        for (int mt = 0; mt < 2; mt++) {
#pragma unroll
            for (int half = 0; half < 2; half++) {
                const int grow = gt + wr * 32 + mt * 16 + (lane >> 2) + half * 8;
                if (grow >= G) continue;
                size_t rb = ((size_t)bm * G + grow) * (size_t)(2 * NOUT);
#pragma unroll
                for (int nt = 0; nt < 4; nt++) {
                    const int col = ntb + wn * 32 + nt * 8 + (lane & 3) * 2;
                    if (col >= NOUT) continue;
                    float v0 = acc[mt][nt][half * 2 + 0] + __ldg(bp + col);
                    float v1 = acc[mt][nt][half * 2 + 1] + __ldg(bp + col + 1);
                    v0 = celu_f(v0);
                    v1 = celu_f(v1);
                    __half h0 = __float2half(v0);
                    __half h1 = __float2half(v1);
                    __half2 hh, ll;
                    hh.x = h0; hh.y = h1;
                    ll.x = __float2half(v0 - __half2float(h0));
                    ll.y = __float2half(v1 - __half2float(h1));
                    *(__half2*)(d_a2 + rb + col) = hh;
                    *(__half2*)(d_a2 + rb + NOUT + col) = ll;
                }
            }
        }
    } else {
        const float* w3 = w3g + (size_t)bm * H2;
#pragma unroll
        for (int mt = 0; mt < 2; mt++) {
#pragma unroll
            for (int half = 0; half < 2; half++) {
                const int grow = gt + wr * 32 + mt * 16 + (lane >> 2) + half * 8;
                float p = 0.f;
#pragma unroll
                for (int nt = 0; nt < 4; nt++) {
                    const int col = ntb + wn * 32 + nt * 8 + (lane & 3) * 2;
                    if (col >= NOUT) continue;
                    float v0 = acc[mt][nt][half * 2 + 0] + __ldg(bp + col);
                    float v1 = acc[mt][nt][half * 2 + 1] + __ldg(bp + col + 1);
                    p = fmaf(celu_f(v0), __ldg(w3 + col), p);
                    p = fmaf(celu_f(v1), __ldg(w3 + col + 1), p);
                }
                p += __shfl_xor_sync(0xFFFFFFFFu, p, 1);
                p += __shfl_xor_sync(0xFFFFFFFFu, p, 2);
                if ((lane & 3) == 0 && grow < G)
                    d_ps[((size_t)bm * G + grow) * 6 + ytile * 2 + wn] = p;
            }
        }
    }
}

// ---------------- deterministic energy reduction -----------------------------
__global__ void k_energy2(const float* __restrict__ b3, int G) {
    const int R = BATCH * G;
    float sum = 0.f;
    for (int r = blockIdx.x * blockDim.x + threadIdx.x; r < R;
         r += gridDim.x * blockDim.x) {
        const int bm = r / G;
        const float* ps = d_ps + (size_t)r * 6;
        sum += ps[0] + ps[1] + ps[2] + ps[3] + ps[4] + ps[5] + b3[bm];
    }
    __shared__ float sh[256];
    sh[threadIdx.x] = sum;
    __syncthreads();
    for (int s = 128; s > 0; s >>= 1) {
        if (threadIdx.x < s) sh[threadIdx.x] += sh[threadIdx.x + s];
        __syncthreads();
    }
    if (threadIdx.x == 0) d_part[blockIdx.x] = sh[0];
}

__global__ void k_final(float* __restrict__ out) {
    __shared__ float sh[EB];
    const int tid = threadIdx.x;
    sh[tid] = d_part[tid];
    __syncthreads();
    for (int s = EB / 2; s > 0; s >>= 1) {
        if (tid < s) sh[tid] += sh[tid + s];
        __syncthreads();
    }
    if (tid == 0) out[0] = sh[0] * (1.0f / (float)MM);
}

// ---------------- harness entry ----------------------------------------------
extern "C" void kernel_launch(void* const* d_in, const int* in_sizes, int n_in,
                              void* d_out, int out_size) {
    const int* species = (const int*)d_in[0];
    const float* aev = (const float*)d_in[1];
    const float* W0 = (const float*)d_in[2];
    const float* b0 = (const float*)d_in[3];
    const float* W1 = (const float*)d_in[4];
    const float* b1 = (const float*)d_in[5];
    const float* W2 = (const float*)d_in[6];
    const float* b2 = (const float*)d_in[7];
    const float* W3 = (const float*)d_in[8];
    const float* b3 = (const float*)d_in[9];
    float* out = (float*)d_out;

    const int N = in_sizes[0];
    const int G = N / SP;
    const int chunk = (N + HB - 1) / HB;

    // bucketing
    k_hist<<<HB, 256>>>(species, N, chunk);
    k_scan<<<1, 32>>>(G);
    k_place<<<HB, 32>>>(species, N, chunk);

    // prep: int8 quant for L0; fp16 transpose for L1/L2
    k_prep_aev_q<<<N, 256>>>(aev);
    k_wmax0<<<BATCH, dim3(H0, 4)>>>(W0);
    k_wquant0<<<dim3(H0 / 32, KQ / 32, BATCH), dim3(32, 8)>>>(W0);
    {
        dim3 g1((H1 + 31) / 32, (H0 + 31) / 32, BATCH);
        k_wsplit<<<g1, dim3(32, 8)>>>(W1, H0, H1, 1);
        dim3 g2((H2 + 31) / 32, (H1 + 31) / 32, BATCH);
        k_wsplit<<<g2, dim3(32, 8)>>>(W2, H1, H2, 2);
    }

    const int gtiles = (G + 127) / 128;
    k_mma0<<<dim3(BATCH, gtiles, H0 / 64), 256>>>(b0, G);
    k_mma<H0, H1, 1><<<dim3(BATCH, gtiles, (H1 + 63) / 64), 256>>>(b1, nullptr, G);
    k_mma<H1, H2, 2><<<dim3(BATCH, gtiles, (H2 + 63) / 64), 256>>>(b2, W3, G);

    k_energy2<<<EB, 256>>>(b3, G);
    k_final<<<1, EB>>>(out);
}

// round 13
// speedup vs baseline: 2.1696x; 2.1696x over previous
#include <cuda_runtime.h>
#include <cuda_fp16.h>
#include <cstdint>

#define SP 7
#define MM 8
#define DD 1008
#define H0 256
#define H1 192
#define H2 160
#define NMAX 50400
#define GMAX (NMAX / SP)
#define BATCH (SP * MM)
#define HB 112
#define EB 1024

// ---------------- scratch (device globals; no allocation allowed) ------------
__device__ int d_idx[NMAX];
__device__ int d_hist[HB * SP];
__device__ int d_off[HB * SP];

// Activations: a0/a1 fp16 [hi | lo] split (rows 2*K); a2 single fp16 (rows K).
// Weights: single fp16.
__device__ __align__(16) __half d_a0[(size_t)NMAX * 2 * DD];
__device__ __align__(16) __half d_w0[(size_t)BATCH * H0 * DD];
__device__ __align__(16) __half d_w1[(size_t)BATCH * H1 * H0];
__device__ __align__(16) __half d_w2[(size_t)BATCH * H2 * H1];
__device__ __align__(16) __half d_a1[(size_t)BATCH * GMAX * 2 * H0];
__device__ __align__(16) __half d_a2[(size_t)BATCH * GMAX * H1];
__device__ float d_ps[(size_t)BATCH * GMAX * 6];   // per-row partial W3 dots
__device__ float d_part[EB];

__device__ __forceinline__ float celu_f(float x) {
    return x > 0.f ? x : 0.1f * expm1f(x * 10.0f);
}

// ---------------- PTX helpers (all baseline sm_80+ features) ------------------
__device__ __forceinline__ uint32_t smem_u32(const void* p) {
    uint32_t a;
    asm("{ .reg .u64 t; cvta.to.shared.u64 t, %1; cvt.u32.u64 %0, t; }"
        : "=r"(a) : "l"(p));
    return a;
}
__device__ __forceinline__ void cp16(uint32_t s, const void* g) {
    asm volatile("cp.async.cg.shared.global [%0], [%1], 16;" :: "r"(s), "l"(g));
}
__device__ __forceinline__ void cp_commit() {
    asm volatile("cp.async.commit_group;" ::: "memory");
}
template <int N>
__device__ __forceinline__ void cp_wait() {
    asm volatile("cp.async.wait_group %0;" :: "n"(N) : "memory");
}
__device__ __forceinline__ void ldsm_x4(uint32_t& r0, uint32_t& r1,
                                        uint32_t& r2, uint32_t& r3, uint32_t a) {
    asm volatile("ldmatrix.sync.aligned.m8n8.x4.shared.b16 {%0,%1,%2,%3}, [%4];"
                 : "=r"(r0), "=r"(r1), "=r"(r2), "=r"(r3) : "r"(a));
}
__device__ __forceinline__ void mma16816(float* c, const uint32_t* a, const uint32_t* b) {
    asm volatile(
        "mma.sync.aligned.m16n8k16.row.col.f32.f16.f16.f32 "
        "{%0,%1,%2,%3}, {%4,%5,%6,%7}, {%8,%9}, {%0,%1,%2,%3};"
        : "+f"(c[0]), "+f"(c[1]), "+f"(c[2]), "+f"(c[3])
        : "r"(a[0]), "r"(a[1]), "r"(a[2]), "r"(a[3]), "r"(b[0]), "r"(b[1]));
}

// ---------------- stable species bucketing (deterministic) -------------------
__global__ void k_hist(const int* __restrict__ sp, int n, int chunk) {
    __shared__ int h[SP];
    if (threadIdx.x < SP) h[threadIdx.x] = 0;
    __syncthreads();
    int b = blockIdx.x;
    int beg = b * chunk, end = min(n, beg + chunk);
    for (int i = beg + threadIdx.x; i < end; i += blockDim.x)
        atomicAdd(&h[sp[i]], 1);
    __syncthreads();
    if (threadIdx.x < SP) d_hist[b * SP + threadIdx.x] = h[threadIdx.x];
}
__global__ void k_scan(int G) {
    int s = threadIdx.x;
    if (s >= SP) return;
    int acc = s * G;
    for (int b = 0; b < HB; b++) { d_off[b * SP + s] = acc; acc += d_hist[b * SP + s]; }
}
__global__ void k_place(const int* __restrict__ sp, int n, int chunk) {
    if (threadIdx.x != 0) return;
    int b = blockIdx.x;
    int beg = b * chunk, end = min(n, beg + chunk);
    int loc[SP];
#pragma unroll
    for (int s = 0; s < SP; s++) loc[s] = d_off[b * SP + s];
    for (int i = beg; i < end; i++) d_idx[loc[sp[i]]++] = i;
}

// ---------------- prep: gather+split AEV (vectorized) ------------------------
__global__ void k_prep_aev(const float* __restrict__ aev) {
    int r = blockIdx.x;
    const float4* src = (const float4*)(aev + (size_t)d_idx[r] * DD);
    __half* dst = d_a0 + (size_t)r * (2 * DD);
    int t = threadIdx.x;
    if (t < DD / 4) {
        float4 v = __ldg(src + t);
        __half h0 = __float2half(v.x), h1 = __float2half(v.y);
        __half h2 = __float2half(v.z), h3 = __float2half(v.w);
        __half2 hA, hB, lA, lB;
        hA.x = h0; hA.y = h1; hB.x = h2; hB.y = h3;
        lA.x = __float2half(v.x - __half2float(h0));
        lA.y = __float2half(v.y - __half2float(h1));
        lB.x = __float2half(v.z - __half2float(h2));
        lB.y = __float2half(v.w - __half2float(h3));
        *(__half2*)(dst + 4 * t) = hA;
        *(__half2*)(dst + 4 * t + 2) = hB;
        *(__half2*)(dst + DD + 4 * t) = lA;
        *(__half2*)(dst + DD + 4 * t + 2) = lB;
    }
}

// ---------------- weight prep: transpose to [n][k], fp16 ---------------------
__global__ void k_wsplit(const float* __restrict__ W, int K, int N, int layer) {
    __shared__ float tile[32][33];
    int bm = blockIdx.z;
    int n0 = blockIdx.x * 32, k0 = blockIdx.y * 32;
    const float* Wp = W + (size_t)bm * K * N;
    for (int r = threadIdx.y; r < 32; r += 8) {
        int k = k0 + r, n = n0 + threadIdx.x;
        tile[r][threadIdx.x] = (k < K && n < N) ? Wp[(size_t)k * N + n] : 0.f;
    }
    __syncthreads();
    __half* O;
    if (layer == 0)      O = d_w0;
    else if (layer == 1) O = d_w1;
    else                 O = d_w2;
    for (int r = threadIdx.y; r < 32; r += 8) {
        int n = n0 + r, k = k0 + threadIdx.x;
        if (n < N && k < K)
            O[((size_t)bm * N + n) * (size_t)K + k] = __float2half(tile[threadIdx.x][r]);
    }
}

// ---------------- fp16 HMMA batched GEMM -------------------------------------
// BM=128, BN=64, BK=16. Grid = (bm, gtile, ytile): bm fastest (L0 A reuse).
// ASPLIT layers (0,1): A = Ah+Al (two products per chunk). LAYER==2: single A.
// Epilogue: +bias, CELU; LAYER==0 -> split store to a1; LAYER==1 -> single
// fp16 store to a2; LAYER==2 -> fused W3 dot -> d_ps partials.
template <int K, int NOUT, int LAYER>
__global__ void __launch_bounds__(256, 2)
k_mma(const float* __restrict__ bias, const float* __restrict__ w3g, int G) {
    constexpr int BM = 128, BN = 64;
    constexpr int TOTAL = K / 16;
    constexpr int NS = 3;
    constexpr bool ASP = (LAYER < 2);
    constexpr int AP = ASP ? 40 : 24;   // smem row pitch in halfs (odd*8)

    __shared__ __align__(16) __half As[NS][BM][AP];
    __shared__ __align__(16) __half Bs[NS][BN][24];

    const int t = threadIdx.x;
    const int lane = t & 31;
    const int wid = t >> 5;
    const int wr = wid >> 1;   // 0..3 -> 32-row slab
    const int wn = wid & 1;    // 0..1 -> 32-col slab
    const int bm = blockIdx.x;          // fastest: models adjacent
    const int gt = blockIdx.y * BM;
    const int ytile = blockIdx.z;
    const int ntb = ytile * BN;

    const __half* Ag;
    const __half* Wg;
    size_t aBase;
    if (LAYER == 0)      { Ag = d_a0; Wg = d_w0; aBase = (size_t)(bm / MM) * G; }
    else if (LAYER == 1) { Ag = d_a1; Wg = d_w1; aBase = (size_t)bm * G; }
    else                 { Ag = d_a2; Wg = d_w2; aBase = (size_t)bm * G; }

    // A: thread t -> row t>>1, 16B segment t&1
    const int arow = t >> 1, aseg = t & 1;
    const int growc = min(gt + arow, G - 1);
    const __half* aSrc =
        Ag + ((size_t)(aBase + growc)) * (size_t)((ASP ? 2 : 1) * K) + aseg * 8;
    // B: threads 0..127 -> row t>>1, segment t&1
    const int brow = t >> 1, bseg = t & 1;
    const int bn = min(ntb + brow, NOUT - 1);
    const __half* bSrc =
        Wg + ((size_t)bm * NOUT + bn) * (size_t)K + bseg * 8;

    auto load_stage = [&](int st, int it) {
        const int k0 = it * 16;
        cp16(smem_u32(&As[st][arow][aseg * 8]), aSrc + k0);               // hi
        if (ASP)
            cp16(smem_u32(&As[st][arow][16 + aseg * 8]), aSrc + K + k0);  // lo
        if (t < 128) cp16(smem_u32(&Bs[st][brow][bseg * 8]), bSrc + k0);
        cp_commit();
    };

    float acc[2][4][4];
#pragma unroll
    for (int i = 0; i < 2; i++)
#pragma unroll
        for (int j = 0; j < 4; j++)
#pragma unroll
            for (int k = 0; k < 4; k++) acc[i][j][k] = 0.f;

    // ldmatrix lane address offsets (bytes)
    const uint32_t aoff =
        (uint32_t)((wr * 32 + (lane & 15)) * (AP * 2) + (lane >> 4) * 16);
    // paired-B x4 (48B pitch)
    const uint32_t boff4 = (uint32_t)(
        (wn * 32 + (lane & 7) + ((lane >> 4) << 3)) * 48 + (((lane >> 3) & 1) * 16));

#pragma unroll 1
    for (int s = 0; s < NS - 1; s++) load_stage(s, s);

#pragma unroll 1
    for (int i = 0; i < TOTAL; i++) {
        cp_wait<NS - 2>();
        __syncthreads();
        if (i + NS - 1 < TOTAL) load_stage((i + NS - 1) % NS, i + NS - 1);
        else cp_commit();

        const int st = i % NS;
        const uint32_t ab = smem_u32(&As[st][0][0]);
        const uint32_t bb = smem_u32(&Bs[st][0][0]);
        uint32_t ah[2][4], al[2][4], bf[4][2];
#pragma unroll
        for (int mt = 0; mt < 2; mt++) {
            ldsm_x4(ah[mt][0], ah[mt][1], ah[mt][2], ah[mt][3],
                    ab + aoff + mt * 16 * (AP * 2));
            if (ASP)
                ldsm_x4(al[mt][0], al[mt][1], al[mt][2], al[mt][3],
                        ab + aoff + mt * 16 * (AP * 2) + 32);
        }
        ldsm_x4(bf[0][0], bf[0][1], bf[1][0], bf[1][1], bb + boff4);
        ldsm_x4(bf[2][0], bf[2][1], bf[3][0], bf[3][1], bb + boff4 + 16 * 48);
#pragma unroll
        for (int mt = 0; mt < 2; mt++)
#pragma unroll
            for (int nt = 0; nt < 4; nt++) {
                mma16816(acc[mt][nt], ah[mt], bf[nt]);
                if (ASP) mma16816(acc[mt][nt], al[mt], bf[nt]);
            }
    }

    // -------- epilogue --------
    const float* bp = bias + (size_t)bm * NOUT;
    if (LAYER == 0) {
#pragma unroll
        for (int mt = 0; mt < 2; mt++) {
#pragma unroll
            for (int half = 0; half < 2; half++) {
                const int grow = gt + wr * 32 + mt * 16 + (lane >> 2) + half * 8;
                if (grow >= G) continue;
                size_t rb = ((size_t)bm * G + grow) * (size_t)(2 * NOUT);
#pragma unroll
                for (int nt = 0; nt < 4; nt++) {
                    const int col = ntb + wn * 32 + nt * 8 + (lane & 3) * 2;
                    float v0 = acc[mt][nt][half * 2 + 0] + __ldg(bp + col);
                    float v1 = acc[mt][nt][half * 2 + 1] + __ldg(bp + col + 1);
                    v0 = celu_f(v0);
                    v1 = celu_f(v1);
                    __half h0 = __float2half(v0);
                    __half h1 = __float2half(v1);
                    __half2 hh, ll;
                    hh.x = h0; hh.y = h1;
                    ll.x = __float2half(v0 - __half2float(h0));
                    ll.y = __float2half(v1 - __half2float(h1));
                    *(__half2*)(d_a1 + rb + col) = hh;
                    *(__half2*)(d_a1 + rb + NOUT + col) = ll;
                }
            }
        }
    } else if (LAYER == 1) {
#pragma unroll
        for (int mt = 0; mt < 2; mt++) {
#pragma unroll
            for (int half = 0; half < 2; half++) {
                const int grow = gt + wr * 32 + mt * 16 + (lane >> 2) + half * 8;
                if (grow >= G) continue;
                size_t rb = ((size_t)bm * G + grow) * (size_t)NOUT;
#pragma unroll
                for (int nt = 0; nt < 4; nt++) {
                    const int col = ntb + wn * 32 + nt * 8 + (lane & 3) * 2;
                    if (col >= NOUT) continue;
                    float v0 = acc[mt][nt][half * 2 + 0] + __ldg(bp + col);
                    float v1 = acc[mt][nt][half * 2 + 1] + __ldg(bp + col + 1);
                    __half2 hh;
                    hh.x = __float2half(celu_f(v0));
                    hh.y = __float2half(celu_f(v1));
                    *(__half2*)(d_a2 + rb + col) = hh;
                }
            }
        }
    } else {
        // fused last-layer dot: p = sum_cols celu(acc+bias)*w3[col]
        const float* w3 = w3g + (size_t)bm * H2;
#pragma unroll
        for (int mt = 0; mt < 2; mt++) {
#pragma unroll
            for (int half = 0; half < 2; half++) {
                const int grow = gt + wr * 32 + mt * 16 + (lane >> 2) + half * 8;
                float p = 0.f;
#pragma unroll
                for (int nt = 0; nt < 4; nt++) {
                    const int col = ntb + wn * 32 + nt * 8 + (lane & 3) * 2;
                    if (col >= NOUT) continue;
                    float v0 = acc[mt][nt][half * 2 + 0] + __ldg(bp + col);
                    float v1 = acc[mt][nt][half * 2 + 1] + __ldg(bp + col + 1);
                    p = fmaf(celu_f(v0), __ldg(w3 + col), p);
                    p = fmaf(celu_f(v1), __ldg(w3 + col + 1), p);
                }
                p += __shfl_xor_sync(0xFFFFFFFFu, p, 1);
                p += __shfl_xor_sync(0xFFFFFFFFu, p, 2);
                if ((lane & 3) == 0 && grow < G)
                    d_ps[((size_t)bm * G + grow) * 6 + ytile * 2 + wn] = p;
            }
        }
    }
}

// ---------------- deterministic energy reduction -----------------------------
__global__ void k_energy2(const float* __restrict__ b3, int G) {
    const int R = BATCH * G;
    float sum = 0.f;
    for (int r = blockIdx.x * blockDim.x + threadIdx.x; r < R;
         r += gridDim.x * blockDim.x) {
        const int bm = r / G;
        const float* ps = d_ps + (size_t)r * 6;
        sum += ps[0] + ps[1] + ps[2] + ps[3] + ps[4] + ps[5] + b3[bm];
    }
    __shared__ float sh[256];
    sh[threadIdx.x] = sum;
    __syncthreads();
    for (int s = 128; s > 0; s >>= 1) {
        if (threadIdx.x < s) sh[threadIdx.x] += sh[threadIdx.x + s];
        __syncthreads();
    }
    if (threadIdx.x == 0) d_part[blockIdx.x] = sh[0];
}

__global__ void k_final(float* __restrict__ out) {
    __shared__ float sh[EB];
    const int tid = threadIdx.x;
    sh[tid] = d_part[tid];
    __syncthreads();
    for (int s = EB / 2; s > 0; s >>= 1) {
        if (tid < s) sh[tid] += sh[tid + s];
        __syncthreads();
    }
    if (tid == 0) out[0] = sh[0] * (1.0f / (float)MM);
}

// ---------------- harness entry ----------------------------------------------
extern "C" void kernel_launch(void* const* d_in, const int* in_sizes, int n_in,
                              void* d_out, int out_size) {
    const int* species = (const int*)d_in[0];
    const float* aev = (const float*)d_in[1];
    const float* W0 = (const float*)d_in[2];
    const float* b0 = (const float*)d_in[3];
    const float* W1 = (const float*)d_in[4];
    const float* b1 = (const float*)d_in[5];
    const float* W2 = (const float*)d_in[6];
    const float* b2 = (const float*)d_in[7];
    const float* W3 = (const float*)d_in[8];
    const float* b3 = (const float*)d_in[9];
    float* out = (float*)d_out;

    const int N = in_sizes[0];
    const int G = N / SP;
    const int chunk = (N + HB - 1) / HB;

    // bucketing
    k_hist<<<HB, 256>>>(species, N, chunk);
    k_scan<<<1, 32>>>(G);
    k_place<<<HB, 32>>>(species, N, chunk);

    // prep: gather+split AEV, transpose weights (fp16)
    k_prep_aev<<<N, 256>>>(aev);
    {
        dim3 g0((H0 + 31) / 32, (DD + 31) / 32, BATCH);
        k_wsplit<<<g0, dim3(32, 8)>>>(W0, DD, H0, 0);
        dim3 g1((H1 + 31) / 32, (H0 + 31) / 32, BATCH);
        k_wsplit<<<g1, dim3(32, 8)>>>(W1, H0, H1, 1);
        dim3 g2((H2 + 31) / 32, (H1 + 31) / 32, BATCH);
        k_wsplit<<<g2, dim3(32, 8)>>>(W2, H1, H2, 2);
    }

    const int gtiles = (G + 127) / 128;
    k_mma<DD, H0, 0><<<dim3(BATCH, gtiles, (H0 + 63) / 64), 256>>>(b0, nullptr, G);
    k_mma<H0, H1, 1><<<dim3(BATCH, gtiles, (H1 + 63) / 64), 256>>>(b1, nullptr, G);
    k_mma<H1, H2, 2><<<dim3(BATCH, gtiles, (H2 + 63) / 64), 256>>>(b2, W3, G);

    k_energy2<<<EB, 256>>>(b3, G);
    k_final<<<1, EB>>>(out);
}

// round 16
// speedup vs baseline: 3.1287x; 1.4421x over previous
#include <cuda_runtime.h>
#include <cuda_fp16.h>
#include <cstdint>

#define SP 7
#define MM 8
#define DD 1008
#define H0 256
#define H1 192
#define H2 160
#define NMAX 50400
#define GMAX (NMAX / SP)
#define BATCH (SP * MM)
#define HB 112
#define EB 1024

// ---------------- scratch (device globals; no allocation allowed) ------------
__device__ int d_idx[NMAX];
__device__ int d_hist[HB * SP];
__device__ int d_off[HB * SP];

// All activations and weights: single fp16, K-contiguous [n][k] rows.
__device__ __align__(16) __half d_a0[(size_t)NMAX * DD];
__device__ __align__(16) __half d_w0[(size_t)BATCH * H0 * DD];
__device__ __align__(16) __half d_w1[(size_t)BATCH * H1 * H0];
__device__ __align__(16) __half d_w2[(size_t)BATCH * H2 * H1];
__device__ __align__(16) __half d_a1[(size_t)BATCH * GMAX * H0];
__device__ __align__(16) __half d_a2[(size_t)BATCH * GMAX * H1];
__device__ float d_ps[(size_t)BATCH * GMAX * 6];   // per-row partial W3 dots
__device__ float d_part[EB];

__device__ __forceinline__ float celu_f(float x) {
    return x > 0.f ? x : 0.1f * expm1f(x * 10.0f);
}

// ---------------- PTX helpers (all baseline sm_80+ features) ------------------
__device__ __forceinline__ uint32_t smem_u32(const void* p) {
    uint32_t a;
    asm("{ .reg .u64 t; cvta.to.shared.u64 t, %1; cvt.u32.u64 %0, t; }"
        : "=r"(a) : "l"(p));
    return a;
}
__device__ __forceinline__ void cp16(uint32_t s, const void* g) {
    asm volatile("cp.async.cg.shared.global [%0], [%1], 16;" :: "r"(s), "l"(g));
}
__device__ __forceinline__ void cp_commit() {
    asm volatile("cp.async.commit_group;" ::: "memory");
}
template <int N>
__device__ __forceinline__ void cp_wait() {
    asm volatile("cp.async.wait_group %0;" :: "n"(N) : "memory");
}
__device__ __forceinline__ void ldsm_x4(uint32_t& r0, uint32_t& r1,
                                        uint32_t& r2, uint32_t& r3, uint32_t a) {
    asm volatile("ldmatrix.sync.aligned.m8n8.x4.shared.b16 {%0,%1,%2,%3}, [%4];"
                 : "=r"(r0), "=r"(r1), "=r"(r2), "=r"(r3) : "r"(a));
}
__device__ __forceinline__ void mma16816(float* c, const uint32_t* a, const uint32_t* b) {
    asm volatile(
        "mma.sync.aligned.m16n8k16.row.col.f32.f16.f16.f32 "
        "{%0,%1,%2,%3}, {%4,%5,%6,%7}, {%8,%9}, {%0,%1,%2,%3};"
        : "+f"(c[0]), "+f"(c[1]), "+f"(c[2]), "+f"(c[3])
        : "r"(a[0]), "r"(a[1]), "r"(a[2]), "r"(a[3]), "r"(b[0]), "r"(b[1]));
}

// ---------------- stable species bucketing (deterministic) -------------------
__global__ void k_hist(const int* __restrict__ sp, int n, int chunk) {
    __shared__ int h[SP];
    if (threadIdx.x < SP) h[threadIdx.x] = 0;
    __syncthreads();
    int b = blockIdx.x;
    int beg = b * chunk, end = min(n, beg + chunk);
    for (int i = beg + threadIdx.x; i < end; i += blockDim.x)
        atomicAdd(&h[sp[i]], 1);
    __syncthreads();
    if (threadIdx.x < SP) d_hist[b * SP + threadIdx.x] = h[threadIdx.x];
}
__global__ void k_scan(int G) {
    int s = threadIdx.x;
    if (s >= SP) return;
    int acc = s * G;
    for (int b = 0; b < HB; b++) { d_off[b * SP + s] = acc; acc += d_hist[b * SP + s]; }
}
__global__ void k_place(const int* __restrict__ sp, int n, int chunk) {
    if (threadIdx.x != 0) return;
    int b = blockIdx.x;
    int beg = b * chunk, end = min(n, beg + chunk);
    int loc[SP];
#pragma unroll
    for (int s = 0; s < SP; s++) loc[s] = d_off[b * SP + s];
    for (int i = beg; i < end; i++) d_idx[loc[sp[i]]++] = i;
}

// ---------------- prep: gather AEV -> fp16 (vectorized) ----------------------
__global__ void k_prep_aev(const float* __restrict__ aev) {
    int r = blockIdx.x;
    const float4* src = (const float4*)(aev + (size_t)d_idx[r] * DD);
    __half* dst = d_a0 + (size_t)r * DD;
    int t = threadIdx.x;
    if (t < DD / 4) {
        float4 v = __ldg(src + t);
        __half2 hA, hB;
        hA.x = __float2half(v.x); hA.y = __float2half(v.y);
        hB.x = __float2half(v.z); hB.y = __float2half(v.w);
        *(__half2*)(dst + 4 * t) = hA;
        *(__half2*)(dst + 4 * t + 2) = hB;
    }
}

// ---------------- weight prep: transpose to [n][k], fp16 ---------------------
__global__ void k_wsplit(const float* __restrict__ W, int K, int N, int layer) {
    __shared__ float tile[32][33];
    int bm = blockIdx.z;
    int n0 = blockIdx.x * 32, k0 = blockIdx.y * 32;
    const float* Wp = W + (size_t)bm * K * N;
    for (int r = threadIdx.y; r < 32; r += 8) {
        int k = k0 + r, n = n0 + threadIdx.x;
        tile[r][threadIdx.x] = (k < K && n < N) ? Wp[(size_t)k * N + n] : 0.f;
    }
    __syncthreads();
    __half* O;
    if (layer == 0)      O = d_w0;
    else if (layer == 1) O = d_w1;
    else                 O = d_w2;
    for (int r = threadIdx.y; r < 32; r += 8) {
        int n = n0 + r, k = k0 + threadIdx.x;
        if (n < N && k < K)
            O[((size_t)bm * N + n) * (size_t)K + k] = __float2half(tile[threadIdx.x][r]);
    }
}

// ---------------- fp16 HMMA batched GEMM (single product) --------------------
// BM=128, BN=64, BK=16. Grid = (bm, gtile, ytile): bm fastest (L0 A reuse).
// Epilogue: +bias, CELU; LAYER==0 -> a1; LAYER==1 -> a2;
//           LAYER==2 -> fused W3 dot -> d_ps partials.
template <int K, int NOUT, int LAYER>
__global__ void __launch_bounds__(256, 2)
k_mma(const float* __restrict__ bias, const float* __restrict__ w3g, int G) {
    constexpr int BM = 128, BN = 64;
    constexpr int TOTAL = K / 16;
    constexpr int NS = 3;

    // rows: [16 elems | 8 pad] = 48B pitch (odd*16B, ldmatrix conflict-free)
    __shared__ __align__(16) __half As[NS][BM][24];
    __shared__ __align__(16) __half Bs[NS][BN][24];

    const int t = threadIdx.x;
    const int lane = t & 31;
    const int wid = t >> 5;
    const int wr = wid >> 1;   // 0..3 -> 32-row slab
    const int wn = wid & 1;    // 0..1 -> 32-col slab
    const int bm = blockIdx.x;          // fastest: models adjacent
    const int gt = blockIdx.y * BM;
    const int ytile = blockIdx.z;
    const int ntb = ytile * BN;

    const __half* Ag;
    const __half* Wg;
    size_t aBase;
    if (LAYER == 0)      { Ag = d_a0; Wg = d_w0; aBase = (size_t)(bm / MM) * G; }
    else if (LAYER == 1) { Ag = d_a1; Wg = d_w1; aBase = (size_t)bm * G; }
    else                 { Ag = d_a2; Wg = d_w2; aBase = (size_t)bm * G; }

    // A: thread t -> row t>>1, 16B segment t&1
    const int arow = t >> 1, aseg = t & 1;
    const int growc = min(gt + arow, G - 1);
    const __half* aSrc = Ag + ((size_t)(aBase + growc)) * (size_t)K + aseg * 8;
    // B: threads 0..127 -> row t>>1, segment t&1
    const int brow = t >> 1, bseg = t & 1;
    const int bn = min(ntb + brow, NOUT - 1);
    const __half* bSrc = Wg + ((size_t)bm * NOUT + bn) * (size_t)K + bseg * 8;

    auto load_stage = [&](int st, int it) {
        const int k0 = it * 16;
        cp16(smem_u32(&As[st][arow][aseg * 8]), aSrc + k0);
        if (t < 128) cp16(smem_u32(&Bs[st][brow][bseg * 8]), bSrc + k0);
        cp_commit();
    };

    float acc[2][4][4];
#pragma unroll
    for (int i = 0; i < 2; i++)
#pragma unroll
        for (int j = 0; j < 4; j++)
#pragma unroll
            for (int k = 0; k < 4; k++) acc[i][j][k] = 0.f;

    // ldmatrix lane address offsets (bytes), 48B pitch
    const uint32_t aoff = (uint32_t)((wr * 32 + (lane & 15)) * 48 + (lane >> 4) * 16);
    // paired-B x4: lanes 0-7 rows r seg0, 8-15 rows r seg1,
    //              16-23 rows r+8 seg0, 24-31 rows r+8 seg1
    const uint32_t boff4 = (uint32_t)(
        (wn * 32 + (lane & 7) + ((lane >> 4) << 3)) * 48 + (((lane >> 3) & 1) * 16));

#pragma unroll 1
    for (int s = 0; s < NS - 1; s++) load_stage(s, s);

#pragma unroll 1
    for (int i = 0; i < TOTAL; i++) {
        cp_wait<NS - 2>();
        __syncthreads();
        if (i + NS - 1 < TOTAL) load_stage((i + NS - 1) % NS, i + NS - 1);
        else cp_commit();

        const int st = i % NS;
        const uint32_t ab = smem_u32(&As[st][0][0]);
        const uint32_t bb = smem_u32(&Bs[st][0][0]);
        uint32_t ah[2][4], bf[4][2];
#pragma unroll
        for (int mt = 0; mt < 2; mt++)
            ldsm_x4(ah[mt][0], ah[mt][1], ah[mt][2], ah[mt][3],
                    ab + aoff + mt * 16 * 48);
        ldsm_x4(bf[0][0], bf[0][1], bf[1][0], bf[1][1], bb + boff4);
        ldsm_x4(bf[2][0], bf[2][1], bf[3][0], bf[3][1], bb + boff4 + 16 * 48);
#pragma unroll
        for (int mt = 0; mt < 2; mt++)
#pragma unroll
            for (int nt = 0; nt < 4; nt++)
                mma16816(acc[mt][nt], ah[mt], bf[nt]);
    }

    // -------- epilogue --------
    const float* bp = bias + (size_t)bm * NOUT;
    if (LAYER < 2) {
        __half* dst = (LAYER == 0) ? d_a1 : d_a2;
#pragma unroll
        for (int mt = 0; mt < 2; mt++) {
#pragma unroll
            for (int half = 0; half < 2; half++) {
                const int grow = gt + wr * 32 + mt * 16 + (lane >> 2) + half * 8;
                if (grow >= G) continue;
                size_t rb = ((size_t)bm * G + grow) * (size_t)NOUT;
#pragma unroll
                for (int nt = 0; nt < 4; nt++) {
                    const int col = ntb + wn * 32 + nt * 8 + (lane & 3) * 2;
                    if (col >= NOUT) continue;
                    float v0 = acc[mt][nt][half * 2 + 0] + __ldg(bp + col);
                    float v1 = acc[mt][nt][half * 2 + 1] + __ldg(bp + col + 1);
                    __half2 hh;
                    hh.x = __float2half(celu_f(v0));
                    hh.y = __float2half(celu_f(v1));
                    *(__half2*)(dst + rb + col) = hh;
                }
            }
        }
    } else {
        // fused last-layer dot: p = sum_cols celu(acc+bias)*w3[col]
        const float* w3 = w3g + (size_t)bm * H2;
#pragma unroll
        for (int mt = 0; mt < 2; mt++) {
#pragma unroll
            for (int half = 0; half < 2; half++) {
                const int grow = gt + wr * 32 + mt * 16 + (lane >> 2) + half * 8;
                float p = 0.f;
#pragma unroll
                for (int nt = 0; nt < 4; nt++) {
                    const int col = ntb + wn * 32 + nt * 8 + (lane & 3) * 2;
                    if (col >= NOUT) continue;
                    float v0 = acc[mt][nt][half * 2 + 0] + __ldg(bp + col);
                    float v1 = acc[mt][nt][half * 2 + 1] + __ldg(bp + col + 1);
                    p = fmaf(celu_f(v0), __ldg(w3 + col), p);
                    p = fmaf(celu_f(v1), __ldg(w3 + col + 1), p);
                }
                p += __shfl_xor_sync(0xFFFFFFFFu, p, 1);
                p += __shfl_xor_sync(0xFFFFFFFFu, p, 2);
                if ((lane & 3) == 0 && grow < G)
                    d_ps[((size_t)bm * G + grow) * 6 + ytile * 2 + wn] = p;
            }
        }
    }
}

// ---------------- deterministic energy reduction -----------------------------
__global__ void k_energy2(const float* __restrict__ b3, int G) {
    const int R = BATCH * G;
    float sum = 0.f;
    for (int r = blockIdx.x * blockDim.x + threadIdx.x; r < R;
         r += gridDim.x * blockDim.x) {
        const int bm = r / G;
        const float* ps = d_ps + (size_t)r * 6;
        sum += ps[0] + ps[1] + ps[2] + ps[3] + ps[4] + ps[5] + b3[bm];
    }
    __shared__ float sh[256];
    sh[threadIdx.x] = sum;
    __syncthreads();
    for (int s = 128; s > 0; s >>= 1) {
        if (threadIdx.x < s) sh[threadIdx.x] += sh[threadIdx.x + s];
        __syncthreads();
    }
    if (threadIdx.x == 0) d_part[blockIdx.x] = sh[0];
}

__global__ void k_final(float* __restrict__ out) {
    __shared__ float sh[EB];
    const int tid = threadIdx.x;
    sh[tid] = d_part[tid];
    __syncthreads();
    for (int s = EB / 2; s > 0; s >>= 1) {
        if (tid < s) sh[tid] += sh[tid + s];
        __syncthreads();
    }
    if (tid == 0) out[0] = sh[0] * (1.0f / (float)MM);
}

// ---------------- harness entry ----------------------------------------------
extern "C" void kernel_launch(void* const* d_in, const int* in_sizes, int n_in,
                              void* d_out, int out_size) {
    const int* species = (const int*)d_in[0];
    const float* aev = (const float*)d_in[1];
    const float* W0 = (const float*)d_in[2];
    const float* b0 = (const float*)d_in[3];
    const float* W1 = (const float*)d_in[4];
    const float* b1 = (const float*)d_in[5];
    const float* W2 = (const float*)d_in[6];
    const float* b2 = (const float*)d_in[7];
    const float* W3 = (const float*)d_in[8];
    const float* b3 = (const float*)d_in[9];
    float* out = (float*)d_out;

    const int N = in_sizes[0];
    const int G = N / SP;
    const int chunk = (N + HB - 1) / HB;

    // bucketing
    k_hist<<<HB, 256>>>(species, N, chunk);
    k_scan<<<1, 32>>>(G);
    k_place<<<HB, 32>>>(species, N, chunk);

    // prep: gather AEV, transpose weights (fp16)
    k_prep_aev<<<N, 256>>>(aev);
    {
        dim3 g0((H0 + 31) / 32, (DD + 31) / 32, BATCH);
        k_wsplit<<<g0, dim3(32, 8)>>>(W0, DD, H0, 0);
        dim3 g1((H1 + 31) / 32, (H0 + 31) / 32, BATCH);
        k_wsplit<<<g1, dim3(32, 8)>>>(W1, H0, H1, 1);
        dim3 g2((H2 + 31) / 32, (H1 + 31) / 32, BATCH);
        k_wsplit<<<g2, dim3(32, 8)>>>(W2, H1, H2, 2);
    }

    const int gtiles = (G + 127) / 128;
    k_mma<DD, H0, 0><<<dim3(BATCH, gtiles, (H0 + 63) / 64), 256>>>(b0, nullptr, G);
    k_mma<H0, H1, 1><<<dim3(BATCH, gtiles, (H1 + 63) / 64), 256>>>(b1, nullptr, G);
    k_mma<H1, H2, 2><<<dim3(BATCH, gtiles, (H2 + 63) / 64), 256>>>(b2, W3, G);

    k_energy2<<<EB, 256>>>(b3, G);
    k_final<<<1, EB>>>(out);
}

// round 17
// speedup vs baseline: 3.1346x; 1.0019x over previous
#include <cuda_runtime.h>
#include <cuda_fp16.h>
#include <cstdint>

#define SP 7
#define MM 8
#define DD 1008
#define H0 256
#define H1 192
#define H2 160
#define NMAX 50400
#define GMAX (NMAX / SP)
#define BATCH (SP * MM)
#define HB 112
#define EB 1024

// ---------------- scratch (device globals; no allocation allowed) ------------
__device__ int d_idx[NMAX];
__device__ int d_hist[HB * SP];
__device__ int d_off[HB * SP];

// All activations and weights: single fp16, K-contiguous [n][k] rows.
__device__ __align__(16) __half d_a0[(size_t)NMAX * DD];
__device__ __align__(16) __half d_w0[(size_t)BATCH * H0 * DD];
__device__ __align__(16) __half d_w1[(size_t)BATCH * H1 * H0];
__device__ __align__(16) __half d_w2[(size_t)BATCH * H2 * H1];
__device__ __align__(16) __half d_a1[(size_t)BATCH * GMAX * H0];
__device__ __align__(16) __half d_a2[(size_t)BATCH * GMAX * H1];
__device__ float d_ps[(size_t)BATCH * GMAX * 6];   // per-row partial W3 dots
__device__ float d_part[EB];

__device__ __forceinline__ float celu_f(float x) {
    return x > 0.f ? x : 0.1f * expm1f(x * 10.0f);
}

// ---------------- PTX helpers (all baseline sm_80+ features) ------------------
__device__ __forceinline__ uint32_t smem_u32(const void* p) {
    uint32_t a;
    asm("{ .reg .u64 t; cvta.to.shared.u64 t, %1; cvt.u32.u64 %0, t; }"
        : "=r"(a) : "l"(p));
    return a;
}
__device__ __forceinline__ void cp16(uint32_t s, const void* g) {
    asm volatile("cp.async.cg.shared.global [%0], [%1], 16;" :: "r"(s), "l"(g));
}
__device__ __forceinline__ void cp_commit() {
    asm volatile("cp.async.commit_group;" ::: "memory");
}
template <int N>
__device__ __forceinline__ void cp_wait() {
    asm volatile("cp.async.wait_group %0;" :: "n"(N) : "memory");
}
__device__ __forceinline__ void ldsm_x4(uint32_t& r0, uint32_t& r1,
                                        uint32_t& r2, uint32_t& r3, uint32_t a) {
    asm volatile("ldmatrix.sync.aligned.m8n8.x4.shared.b16 {%0,%1,%2,%3}, [%4];"
                 : "=r"(r0), "=r"(r1), "=r"(r2), "=r"(r3) : "r"(a));
}
__device__ __forceinline__ void mma16816(float* c, const uint32_t* a, const uint32_t* b) {
    asm volatile(
        "mma.sync.aligned.m16n8k16.row.col.f32.f16.f16.f32 "
        "{%0,%1,%2,%3}, {%4,%5,%6,%7}, {%8,%9}, {%0,%1,%2,%3};"
        : "+f"(c[0]), "+f"(c[1]), "+f"(c[2]), "+f"(c[3])
        : "r"(a[0]), "r"(a[1]), "r"(a[2]), "r"(a[3]), "r"(b[0]), "r"(b[1]));
}

// ---------------- stable species bucketing (deterministic) -------------------
__global__ void k_hist(const int* __restrict__ sp, int n, int chunk) {
    __shared__ int h[SP];
    if (threadIdx.x < SP) h[threadIdx.x] = 0;
    __syncthreads();
    int b = blockIdx.x;
    int beg = b * chunk, end = min(n, beg + chunk);
    for (int i = beg + threadIdx.x; i < end; i += blockDim.x)
        atomicAdd(&h[sp[i]], 1);
    __syncthreads();
    if (threadIdx.x < SP) d_hist[b * SP + threadIdx.x] = h[threadIdx.x];
}
__global__ void k_scan(int G) {
    int s = threadIdx.x;
    if (s >= SP) return;
    int acc = s * G;
    for (int b = 0; b < HB; b++) { d_off[b * SP + s] = acc; acc += d_hist[b * SP + s]; }
}
__global__ void k_place(const int* __restrict__ sp, int n, int chunk) {
    if (threadIdx.x != 0) return;
    int b = blockIdx.x;
    int beg = b * chunk, end = min(n, beg + chunk);
    int loc[SP];
#pragma unroll
    for (int s = 0; s < SP; s++) loc[s] = d_off[b * SP + s];
    for (int i = beg; i < end; i++) d_idx[loc[sp[i]]++] = i;
}

// ---------------- prep: gather AEV -> fp16 (vectorized) ----------------------
__global__ void k_prep_aev(const float* __restrict__ aev) {
    int r = blockIdx.x;
    const float4* src = (const float4*)(aev + (size_t)d_idx[r] * DD);
    __half* dst = d_a0 + (size_t)r * DD;
    int t = threadIdx.x;
    if (t < DD / 4) {
        float4 v = __ldg(src + t);
        __half2 hA, hB;
        hA.x = __float2half(v.x); hA.y = __float2half(v.y);
        hB.x = __float2half(v.z); hB.y = __float2half(v.w);
        *(__half2*)(dst + 4 * t) = hA;
        *(__half2*)(dst + 4 * t + 2) = hB;
    }
}

// ---------------- weight prep: transpose to [n][k], fp16 ---------------------
__global__ void k_wsplit(const float* __restrict__ W, int K, int N, int layer) {
    __shared__ float tile[32][33];
    int bm = blockIdx.z;
    int n0 = blockIdx.x * 32, k0 = blockIdx.y * 32;
    const float* Wp = W + (size_t)bm * K * N;
    for (int r = threadIdx.y; r < 32; r += 8) {
        int k = k0 + r, n = n0 + threadIdx.x;
        tile[r][threadIdx.x] = (k < K && n < N) ? Wp[(size_t)k * N + n] : 0.f;
    }
    __syncthreads();
    __half* O;
    if (layer == 0)      O = d_w0;
    else if (layer == 1) O = d_w1;
    else                 O = d_w2;
    for (int r = threadIdx.y; r < 32; r += 8) {
        int n = n0 + r, k = k0 + threadIdx.x;
        if (n < N && k < K)
            O[((size_t)bm * N + n) * (size_t)K + k] = __float2half(tile[threadIdx.x][r]);
    }
}

// ---------------- fp16 HMMA batched GEMM (single product) --------------------
// BM=128, BN=64, BK=16. Grid = (bm, gtile, ytile): bm fastest (L0 A reuse).
// Epilogue: +bias, CELU; LAYER==0 -> a1; LAYER==1 -> a2;
//           LAYER==2 -> fused W3 dot -> d_ps partials.
template <int K, int NOUT, int LAYER>
__global__ void __launch_bounds__(256, 2)
k_mma(const float* __restrict__ bias, const float* __restrict__ w3g, int G) {
    constexpr int BM = 128, BN = 64;
    constexpr int TOTAL = K / 16;
    constexpr int NS = 3;

    // rows: [16 elems | 8 pad] = 48B pitch (odd*16B, ldmatrix conflict-free)
    __shared__ __align__(16) __half As[NS][BM][24];
    __shared__ __align__(16) __half Bs[NS][BN][24];

    const int t = threadIdx.x;
    const int lane = t & 31;
    const int wid = t >> 5;
    const int wr = wid >> 1;   // 0..3 -> 32-row slab
    const int wn = wid & 1;    // 0..1 -> 32-col slab
    const int bm = blockIdx.x;          // fastest: models adjacent
    const int gt = blockIdx.y * BM;
    const int ytile = blockIdx.z;
    const int ntb = ytile * BN;

    const __half* Ag;
    const __half* Wg;
    size_t aBase;
    if (LAYER == 0)      { Ag = d_a0; Wg = d_w0; aBase = (size_t)(bm / MM) * G; }
    else if (LAYER == 1) { Ag = d_a1; Wg = d_w1; aBase = (size_t)bm * G; }
    else                 { Ag = d_a2; Wg = d_w2; aBase = (size_t)bm * G; }

    // A: thread t -> row t>>1, 16B segment t&1
    const int arow = t >> 1, aseg = t & 1;
    const int growc = min(gt + arow, G - 1);
    const __half* aSrc = Ag + ((size_t)(aBase + growc)) * (size_t)K + aseg * 8;
    // B: threads 0..127 -> row t>>1, segment t&1
    const int brow = t >> 1, bseg = t & 1;
    const int bn = min(ntb + brow, NOUT - 1);
    const __half* bSrc = Wg + ((size_t)bm * NOUT + bn) * (size_t)K + bseg * 8;

    auto load_stage = [&](int st, int it) {
        const int k0 = it * 16;
        cp16(smem_u32(&As[st][arow][aseg * 8]), aSrc + k0);
        if (t < 128) cp16(smem_u32(&Bs[st][brow][bseg * 8]), bSrc + k0);
        cp_commit();
    };

    float acc[2][4][4];
#pragma unroll
    for (int i = 0; i < 2; i++)
#pragma unroll
        for (int j = 0; j < 4; j++)
#pragma unroll
            for (int k = 0; k < 4; k++) acc[i][j][k] = 0.f;

    // ldmatrix lane address offsets (bytes), 48B pitch
    const uint32_t aoff = (uint32_t)((wr * 32 + (lane & 15)) * 48 + (lane >> 4) * 16);
    // paired-B x4: lanes 0-7 rows r seg0, 8-15 rows r seg1,
    //              16-23 rows r+8 seg0, 24-31 rows r+8 seg1
    const uint32_t boff4 = (uint32_t)(
        (wn * 32 + (lane & 7) + ((lane >> 4) << 3)) * 48 + (((lane >> 3) & 1) * 16));

#pragma unroll 1
    for (int s = 0; s < NS - 1; s++) load_stage(s, s);

#pragma unroll 1
    for (int i = 0; i < TOTAL; i++) {
        cp_wait<NS - 2>();
        __syncthreads();
        if (i + NS - 1 < TOTAL) load_stage((i + NS - 1) % NS, i + NS - 1);
        else cp_commit();

        const int st = i % NS;
        const uint32_t ab = smem_u32(&As[st][0][0]);
        const uint32_t bb = smem_u32(&Bs[st][0][0]);
        uint32_t ah[2][4], bf[4][2];
#pragma unroll
        for (int mt = 0; mt < 2; mt++)
            ldsm_x4(ah[mt][0], ah[mt][1], ah[mt][2], ah[mt][3],
                    ab + aoff + mt * 16 * 48);
        ldsm_x4(bf[0][0], bf[0][1], bf[1][0], bf[1][1], bb + boff4);
        ldsm_x4(bf[2][0], bf[2][1], bf[3][0], bf[3][1], bb + boff4 + 16 * 48);
#pragma unroll
        for (int mt = 0; mt < 2; mt++)
#pragma unroll
            for (int nt = 0; nt < 4; nt++)
                mma16816(acc[mt][nt], ah[mt], bf[nt]);
    }

    // -------- epilogue --------
    const float* bp = bias + (size_t)bm * NOUT;
    if (LAYER < 2) {
        __half* dst = (LAYER == 0) ? d_a1 : d_a2;
#pragma unroll
        for (int mt = 0; mt < 2; mt++) {
#pragma unroll
            for (int half = 0; half < 2; half++) {
                const int grow = gt + wr * 32 + mt * 16 + (lane >> 2) + half * 8;
                if (grow >= G) continue;
                size_t rb = ((size_t)bm * G + grow) * (size_t)NOUT;
#pragma unroll
                for (int nt = 0; nt < 4; nt++) {
                    const int col = ntb + wn * 32 + nt * 8 + (lane & 3) * 2;
                    if (col >= NOUT) continue;
                    float v0 = acc[mt][nt][half * 2 + 0] + __ldg(bp + col);
                    float v1 = acc[mt][nt][half * 2 + 1] + __ldg(bp + col + 1);
                    __half2 hh;
                    hh.x = __float2half(celu_f(v0));
                    hh.y = __float2half(celu_f(v1));
                    *(__half2*)(dst + rb + col) = hh;
                }
            }
        }
    } else {
        // fused last-layer dot: p = sum_cols celu(acc+bias)*w3[col]
        const float* w3 = w3g + (size_t)bm * H2;
#pragma unroll
        for (int mt = 0; mt < 2; mt++) {
#pragma unroll
            for (int half = 0; half < 2; half++) {
                const int grow = gt + wr * 32 + mt * 16 + (lane >> 2) + half * 8;
                float p = 0.f;
#pragma unroll
                for (int nt = 0; nt < 4; nt++) {
                    const int col = ntb + wn * 32 + nt * 8 + (lane & 3) * 2;
                    if (col >= NOUT) continue;
                    float v0 = acc[mt][nt][half * 2 + 0] + __ldg(bp + col);
                    float v1 = acc[mt][nt][half * 2 + 1] + __ldg(bp + col + 1);
                    p = fmaf(celu_f(v0), __ldg(w3 + col), p);
                    p = fmaf(celu_f(v1), __ldg(w3 + col + 1), p);
                }
                p += __shfl_xor_sync(0xFFFFFFFFu, p, 1);
                p += __shfl_xor_sync(0xFFFFFFFFu, p, 2);
                if ((lane & 3) == 0 && grow < G)
                    d_ps[((size_t)bm * G + grow) * 6 + ytile * 2 + wn] = p;
            }
        }
    }
}

// ---------------- deterministic energy reduction -----------------------------
__global__ void k_energy2(const float* __restrict__ b3, int G) {
    const int R = BATCH * G;
    float sum = 0.f;
    for (int r = blockIdx.x * blockDim.x + threadIdx.x; r < R;
         r += gridDim.x * blockDim.x) {
        const int bm = r / G;
        const float* ps = d_ps + (size_t)r * 6;
        sum += ps[0] + ps[1] + ps[2] + ps[3] + ps[4] + ps[5] + b3[bm];
    }
    __shared__ float sh[256];
    sh[threadIdx.x] = sum;
    __syncthreads();
    for (int s = 128; s > 0; s >>= 1) {
        if (threadIdx.x < s) sh[threadIdx.x] += sh[threadIdx.x + s];
        __syncthreads();
    }
    if (threadIdx.x == 0) d_part[blockIdx.x] = sh[0];
}

__global__ void k_final(float* __restrict__ out) {
    __shared__ float sh[EB];
    const int tid = threadIdx.x;
    sh[tid] = d_part[tid];
    __syncthreads();
    for (int s = EB / 2; s > 0; s >>= 1) {
        if (tid < s) sh[tid] += sh[tid + s];
        __syncthreads();
    }
    if (tid == 0) out[0] = sh[0] * (1.0f / (float)MM);
}

// ---------------- harness entry ----------------------------------------------
extern "C" void kernel_launch(void* const* d_in, const int* in_sizes, int n_in,
                              void* d_out, int out_size) {
    const int* species = (const int*)d_in[0];
    const float* aev = (const float*)d_in[1];
    const float* W0 = (const float*)d_in[2];
    const float* b0 = (const float*)d_in[3];
    const float* W1 = (const float*)d_in[4];
    const float* b1 = (const float*)d_in[5];
    const float* W2 = (const float*)d_in[6];
    const float* b2 = (const float*)d_in[7];
    const float* W3 = (const float*)d_in[8];
    const float* b3 = (const float*)d_in[9];
    float* out = (float*)d_out;

    const int N = in_sizes[0];
    const int G = N / SP;
    const int chunk = (N + HB - 1) / HB;

    // bucketing
    k_hist<<<HB, 256>>>(species, N, chunk);
    k_scan<<<1, 32>>>(G);
    k_place<<<HB, 32>>>(species, N, chunk);

    // prep: gather AEV, transpose weights (fp16)
    k_prep_aev<<<N, 256>>>(aev);
    {
        dim3 g0((H0 + 31) / 32, (DD + 31) / 32, BATCH);
        k_wsplit<<<g0, dim3(32, 8)>>>(W0, DD, H0, 0);
        dim3 g1((H1 + 31) / 32, (H0 + 31) / 32, BATCH);
        k_wsplit<<<g1, dim3(32, 8)>>>(W1, H0, H1, 1);
        dim3 g2((H2 + 31) / 32, (H1 + 31) / 32, BATCH);
        k_wsplit<<<g2, dim3(32, 8)>>>(W2, H1, H2, 2);
    }

    const int gtiles = (G + 127) / 128;
    k_mma<DD, H0, 0><<<dim3(BATCH, gtiles, (H0 + 63) / 64), 256>>>(b0, nullptr, G);
    k_mma<H0, H1, 1><<<dim3(BATCH, gtiles, (H1 + 63) / 64), 256>>>(b1, nullptr, G);
    k_mma<H1, H2, 2><<<dim3(BATCH, gtiles, (H2 + 63) / 64), 256>>>(b2, W3, G);

    k_energy2<<<EB, 256>>>(b3, G);
    k_final<<<1, EB>>>(out);
}